// round 1
// baseline (speedup 1.0000x reference)
#include <cuda_runtime.h>

#define DEVINL __device__ __forceinline__

namespace {

constexpr int NOFF = 44;
constexpr int H    = 16;
constexpr int N    = 8192;
constexpr int HD   = 64;
constexpr int POS_PER_CTA = 64;
constexpr int NTHREADS    = 256;
constexpr float SC = 0.125f;   // 1/sqrt(64)
constexpr int MAX_OFF = 1536;

// Offsets: 0..32 dense, then sparse tail. constexpr function so it folds at
// compile time inside fully-unrolled loops (no constant-bank loads, no
// relaxed-constexpr dependency).
__host__ __device__ constexpr int off_at(int i) {
    return i <= 32 ? i
         : i == 33 ? 48   : i == 34 ? 64   : i == 35 ? 96
         : i == 36 ? 128  : i == 37 ? 192  : i == 38 ? 256
         : i == 39 ? 384  : i == 40 ? 512  : i == 41 ? 768
         : i == 42 ? 1024 : 1536;
}

struct Smem {
    float  se[NOFF * HD];   // 11264 B
    float  bias[NOFF];      // pos_bias[:, h]
    float2 cs[NOFF];        // (cos(phase), sin(phase)) for this h
};

// One 16-lane group handles one position n; lane covers dims [4c, 4c+4).
template <bool CHECK>
DEVINL void run_pos(int n, int c,
                    const float* __restrict__ qb,
                    const float* __restrict__ kb,
                    const float* __restrict__ vb,
                    float* __restrict__ ob,
                    const Smem& sm)
{
    const float4 q4 = *reinterpret_cast<const float4*>(qb + (size_t)n * HD + 4 * c);

    float s[NOFF];

    // ---- score phase: s_i = sc * (q . (k[n-d] + se_i)) + bias_i ----
#pragma unroll
    for (int i = 0; i < NOFF; ++i) {
        const int d = off_at(i);
        const bool valid = !CHECK || (n >= d);
        float4 k4;
        if (valid) k4 = *reinterpret_cast<const float4*>(kb + (size_t)(n - d) * HD + 4 * c);
        else       k4 = make_float4(0.f, 0.f, 0.f, 0.f);
        const float4 se4 = *reinterpret_cast<const float4*>(&sm.se[i * HD + 4 * c]);

        float hsum = q4.x * (k4.x + se4.x)
                   + q4.y * (k4.y + se4.y)
                   + q4.z * (k4.z + se4.z)
                   + q4.w * (k4.w + se4.w);
        // butterfly over the 16-lane group (masks < 16 stay in-group)
        hsum += __shfl_xor_sync(0xffffffffu, hsum, 1);
        hsum += __shfl_xor_sync(0xffffffffu, hsum, 2);
        hsum += __shfl_xor_sync(0xffffffffu, hsum, 4);
        hsum += __shfl_xor_sync(0xffffffffu, hsum, 8);

        s[i] = valid ? fmaf(hsum, SC, sm.bias[i]) : -1e30f;
    }

    // ---- softmax over 44 (normalization deferred) ----
    float m = s[0];
#pragma unroll
    for (int i = 1; i < NOFF; ++i) m = fmaxf(m, s[i]);
    float sum = 0.f;
#pragma unroll
    for (int i = 0; i < NOFF; ++i) {
        float e = __expf(s[i] - m);
        s[i] = e;
        sum += e;
    }
    const float inv = __fdividef(1.f, sum);

    // ---- output phase: out += e_i * R(phase_i) v[n-d]; scale by inv at end ----
    float4 o = make_float4(0.f, 0.f, 0.f, 0.f);
#pragma unroll
    for (int i = 0; i < NOFF; ++i) {
        const int d = off_at(i);
        const bool valid = !CHECK || (n >= d);
        float4 v4;
        if (valid) v4 = *reinterpret_cast<const float4*>(vb + (size_t)(n - d) * HD + 4 * c);
        else       v4 = make_float4(0.f, 0.f, 0.f, 0.f);

        const float2 cs = sm.cs[i];
        const float a = s[i] * cs.x;   // e_i * cos
        const float b = s[i] * cs.y;   // e_i * sin

        o.x = fmaf(a, v4.x, o.x);  o.x = fmaf(-b, v4.y, o.x);
        o.y = fmaf(b, v4.x, o.y);  o.y = fmaf( a, v4.y, o.y);
        o.z = fmaf(a, v4.z, o.z);  o.z = fmaf(-b, v4.w, o.z);
        o.w = fmaf(b, v4.z, o.w);  o.w = fmaf( a, v4.w, o.w);
    }
    o.x *= inv; o.y *= inv; o.z *= inv; o.w *= inv;

    *reinterpret_cast<float4*>(ob + (size_t)n * HD + 4 * c) = o;
}

__global__ void __launch_bounds__(NTHREADS)
dsqg_kernel(const float* __restrict__ q, const float* __restrict__ k,
            const float* __restrict__ v, const float* __restrict__ pos_bias,
            const float* __restrict__ se, const float* __restrict__ phase,
            float* __restrict__ out)
{
    __shared__ Smem sm;
    const int bh  = blockIdx.y;
    const int h   = bh & (H - 1);
    const int tid = threadIdx.x;

    for (int idx = tid; idx < NOFF * HD; idx += NTHREADS) sm.se[idx] = se[idx];
    if (tid < NOFF) {
        sm.bias[tid] = pos_bias[tid * H + h];
        float ss, cc;
        sincosf(phase[tid * H + h], &ss, &cc);
        sm.cs[tid] = make_float2(cc, ss);
    }
    __syncthreads();

    const size_t base = (size_t)bh * N * HD;
    const float* qb = q + base;
    const float* kb = k + base;
    const float* vb = v + base;
    float*       ob = out + base;

    const int warp = tid >> 5;
    const int lane = tid & 31;
    const int sub  = lane >> 4;   // which of the warp's 2 positions
    const int c    = lane & 15;   // dim chunk
    const int n0   = blockIdx.x * POS_PER_CTA;

    if (n0 >= MAX_OFF) {
        // all offsets valid for every position in this tile: no masking
#pragma unroll 1
        for (int it = 0; it < POS_PER_CTA / 16; ++it) {
            const int n = n0 + it * 16 + warp * 2 + sub;
            run_pos<false>(n, c, qb, kb, vb, ob, sm);
        }
    } else {
#pragma unroll 1
        for (int it = 0; it < POS_PER_CTA / 16; ++it) {
            const int n = n0 + it * 16 + warp * 2 + sub;
            run_pos<true>(n, c, qb, kb, vb, ob, sm);
        }
    }
}

} // namespace

extern "C" void kernel_launch(void* const* d_in, const int* in_sizes, int n_in,
                              void* d_out, int out_size)
{
    const float* q  = (const float*)d_in[0];
    const float* k  = (const float*)d_in[1];
    const float* v  = (const float*)d_in[2];
    const float* pb = (const float*)d_in[3];
    const float* se = (const float*)d_in[4];
    const float* ph = (const float*)d_in[5];
    float* out = (float*)d_out;

    const int B = in_sizes[0] / (H * N * HD);   // expect 2
    dim3 grid(N / POS_PER_CTA, B * H);
    dsqg_kernel<<<grid, NTHREADS>>>(q, k, v, pb, se, ph, out);
}